// round 4
// baseline (speedup 1.0000x reference)
#include <cuda_runtime.h>
#include <math.h>

#define NMAX 100000
#define EMAX 1600000
#define HEADS 8

typedef unsigned long long ull;

// ---------------- scratch (static device globals; no runtime alloc) ----------------
__device__ float g_xh1[(size_t)NMAX * 256];
__device__ float g_xh2[(size_t)NMAX * 128];
__device__ float g_asrc[(size_t)NMAX * HEADS];
__device__ float g_adst[(size_t)NMAX * HEADS];
__device__ float g_h1[(size_t)NMAX * 32];
__device__ int   g_deg[NMAX];
__device__ int   g_off[NMAX + 1];
__device__ int   g_cursor[NMAX];
__device__ int   g_srcs[(size_t)(EMAX + NMAX)];

// ---------------- helpers ----------------
__device__ __forceinline__ float lrelu_exp(float v) {
    v = v > 0.0f ? v : 0.2f * v;
    return expf(v);
}
__device__ __forceinline__ ull pack2(float v) {
    ull r; asm("mov.b64 %0, {%1, %1};" : "=l"(r) : "f"(v)); return r;
}
__device__ __forceinline__ void fma2(ull& d, ull a, ull b) {
    asm("fma.rn.f32x2 %0, %1, %2, %0;" : "+l"(d) : "l"(a), "l"(b));
}
__device__ __forceinline__ float2 unpack2(ull v) {
    float2 f; asm("mov.b64 {%0, %1}, %2;" : "=f"(f.x), "=f"(f.y) : "l"(v)); return f;
}

// ---------------- CSR build: count, scan, copy, scatter (by dst) ----------------
__global__ void hist_kernel(const int* __restrict__ ei, int E, int* __restrict__ deg) {
    for (int k = blockIdx.x * blockDim.x + threadIdx.x; k < E; k += gridDim.x * blockDim.x)
        atomicAdd(&deg[__ldg(ei + E + k)], 1);
}

__global__ void scan_kernel(const int* __restrict__ deg, int* __restrict__ off, int N) {
    __shared__ int s[1024];
    int tid = threadIdx.x;
    int CH = (N + 1023) >> 10;
    int b = tid * CH;
    int e = min(b + CH, N);
    int sum = 0;
    for (int i = b; i < e; i++) sum += deg[i] + 1;   // +1 self loop
    s[tid] = sum;
    __syncthreads();
    for (int d = 1; d < 1024; d <<= 1) {
        int v = (tid >= d) ? s[tid - d] : 0;
        __syncthreads();
        s[tid] += v;
        __syncthreads();
    }
    int run = s[tid] - sum;   // exclusive prefix
    for (int i = b; i < e; i++) { off[i] = run; run += deg[i] + 1; }
    if (tid == 1023) off[N] = run;
}

__global__ void copy_kernel(const int* __restrict__ off, int* __restrict__ cursor, int N) {
    int i = blockIdx.x * blockDim.x + threadIdx.x;
    if (i < N) cursor[i] = off[i];
}

__global__ void scatter_kernel(const int* __restrict__ ei, int E, int N,
                               int* __restrict__ cursor, int* __restrict__ srcs) {
    int EN = E + N;
    for (int k = blockIdx.x * blockDim.x + threadIdx.x; k < EN; k += gridDim.x * blockDim.x) {
        int src, dst;
        if (k < E) { src = __ldg(ei + k); dst = __ldg(ei + E + k); }
        else       { src = dst = k - E; }
        int pos = atomicAdd(&cursor[dst], 1);
        srcs[pos] = src;
    }
}

// ---------------- fused GEMM (fp32x2) + attention logits; CO split across gridDim.y ----------------
// block: 512 threads; cg = lane (32 column quads), rg = warp (16 row groups x 4 rows = 64 rows).
template<int F, int CO, int HS>
__global__ void gemm_att_kernel(const float* __restrict__ X, const float* __restrict__ W,
                                const float* __restrict__ a_src_w, const float* __restrict__ a_dst_w,
                                float* __restrict__ XH, float* __restrict__ ASRC,
                                float* __restrict__ ADST, int N) {
    constexpr int GROUP = HS / 4;                 // quads per head
    extern __shared__ float sh[];
    float* Ws = sh;                                // F * 128 floats
    float* Xs = sh + F * 128;                      // 64 * F floats
    float4* Ws4 = reinterpret_cast<float4*>(Ws);
    const ulonglong2* Wsu = reinterpret_cast<const ulonglong2*>(Ws);
    float4* Xs4 = reinterpret_cast<float4*>(Xs);

    const int tid  = threadIdx.x;
    const int cg   = tid & 31;
    const int rg   = tid >> 5;
    const int half = blockIdx.y;                   // column half index
    const int qg   = half * 32 + cg;               // global column quad

    // load W slice [F, 128 cols] into shared
    const float4* Wg4 = reinterpret_cast<const float4*>(W);
    for (int i = tid; i < F * 32; i += 512) {
        int f = i >> 5, c = i & 31;
        Ws4[i] = Wg4[(size_t)f * (CO / 4) + half * 32 + c];
    }

    const float4 av_s = reinterpret_cast<const float4*>(a_src_w)[qg];
    const float4 av_d = reinterpret_cast<const float4*>(a_dst_w)[qg];

    const int n0 = blockIdx.x * 64;
    // load X tile [64, F]
    for (int i = tid; i < 64 * F / 4; i += 512) {
        int row  = i / (F / 4);
        int col4 = i % (F / 4);
        int n = n0 + row;
        Xs4[i] = (n < N) ? reinterpret_cast<const float4*>(X)[(size_t)n * (F / 4) + col4]
                         : make_float4(0.f, 0.f, 0.f, 0.f);
    }
    __syncthreads();

    ull acc[4][2];
    #pragma unroll
    for (int r = 0; r < 4; r++) { acc[r][0] = 0ULL; acc[r][1] = 0ULL; }

    #pragma unroll 8
    for (int f = 0; f < F; f++) {
        ulonglong2 w = Wsu[f * 32 + cg];
        #pragma unroll
        for (int r = 0; r < 4; r++) {
            ull xv2 = pack2(Xs[(rg * 4 + r) * F + f]);
            fma2(acc[r][0], xv2, w.x);
            fma2(acc[r][1], xv2, w.y);
        }
    }

    #pragma unroll
    for (int r = 0; r < 4; r++) {
        int n = n0 + rg * 4 + r;
        if (n >= N) continue;
        float2 lo = unpack2(acc[r][0]);
        float2 hi = unpack2(acc[r][1]);
        float4 o = make_float4(lo.x, lo.y, hi.x, hi.y);
        reinterpret_cast<float4*>(XH)[(size_t)n * (CO / 4) + qg] = o;
        float ps = o.x * av_s.x + o.y * av_s.y + o.z * av_s.z + o.w * av_s.w;
        float pd = o.x * av_d.x + o.y * av_d.y + o.z * av_d.z + o.w * av_d.w;
        #pragma unroll
        for (int s = GROUP / 2; s > 0; s >>= 1) {
            ps += __shfl_xor_sync(0xffffffffu, ps, s);
            pd += __shfl_xor_sync(0xffffffffu, pd, s);
        }
        if ((cg & (GROUP - 1)) == 0) {
            int h = qg / GROUP;
            ASRC[(size_t)n * HEADS + h] = ps;
            ADST[(size_t)n * HEADS + h] = pd;
        }
    }
}

// ---------------- layer-1 aggregation: warp per dst, fused den+agg+mean+bias+ELU ----------------
__global__ void agg1_kernel(const int* __restrict__ off, const int* __restrict__ srcs,
                            const float* __restrict__ XH,
                            const float* __restrict__ ASRC, const float* __restrict__ ADST,
                            const float* __restrict__ b, float* __restrict__ H1, int N) {
    int w = (blockIdx.x * blockDim.x + threadIdx.x) >> 5;
    if (w >= N) return;
    int lane  = threadIdx.x & 31;
    int e_sub = lane >> 3;      // 0..3: parallel edge slot
    int hl    = lane & 7;       // head (pass A) / dim quad (pass B)

    int beg = __ldg(off + w);
    int end = __ldg(off + w + 1);
    int niter = (end - beg + 3) >> 2;
    float adst_h = __ldg(ADST + (size_t)w * 8 + hl);

    // pass A: denominator per head
    float den = 0.f;
    for (int it = 0; it < niter; it++) {
        int p = beg + it * 4 + e_sub;
        bool v = p < end;
        int s = __ldg(srcs + (v ? p : beg));
        float e = lrelu_exp(__ldg(ASRC + (size_t)s * 8 + hl) + adst_h);
        den += v ? e : 0.f;
    }
    den += __shfl_xor_sync(0xffffffffu, den, 8);
    den += __shfl_xor_sync(0xffffffffu, den, 16);
    float inv = 1.0f / den;

    // pass B: accumulate sum_h alpha_h * xh[src, h, quad hl]
    float4 acc = make_float4(0.f, 0.f, 0.f, 0.f);
    for (int it = 0; it < niter; it++) {
        int p = beg + it * 4 + e_sub;
        bool v = p < end;
        int s = __ldg(srcs + (v ? p : beg));
        float myal = v ? lrelu_exp(__ldg(ASRC + (size_t)s * 8 + hl) + adst_h) * inv : 0.f;
        const float4* xs = reinterpret_cast<const float4*>(XH) + (size_t)s * 64;
        #pragma unroll
        for (int h = 0; h < 8; h++) {
            float al = __shfl_sync(0xffffffffu, myal, (e_sub << 3) + h);
            float4 xv = __ldg(xs + h * 8 + hl);
            acc.x += al * xv.x; acc.y += al * xv.y;
            acc.z += al * xv.z; acc.w += al * xv.w;
        }
    }
    // reduce across the 4 edge slots
    #pragma unroll
    for (int s = 8; s <= 16; s <<= 1) {
        acc.x += __shfl_xor_sync(0xffffffffu, acc.x, s);
        acc.y += __shfl_xor_sync(0xffffffffu, acc.y, s);
        acc.z += __shfl_xor_sync(0xffffffffu, acc.z, s);
        acc.w += __shfl_xor_sync(0xffffffffu, acc.w, s);
    }
    if (e_sub == 0) {
        float4 bv = reinterpret_cast<const float4*>(b)[hl];
        float4 o;
        o.x = acc.x * 0.125f + bv.x;
        o.y = acc.y * 0.125f + bv.y;
        o.z = acc.z * 0.125f + bv.z;
        o.w = acc.w * 0.125f + bv.w;
        o.x = o.x > 0.f ? o.x : expf(o.x) - 1.0f;
        o.y = o.y > 0.f ? o.y : expf(o.y) - 1.0f;
        o.z = o.z > 0.f ? o.z : expf(o.z) - 1.0f;
        o.w = o.w > 0.f ? o.w : expf(o.w) - 1.0f;
        reinterpret_cast<float4*>(H1)[(size_t)w * 8 + hl] = o;
    }
}

// ---------------- layer-2 aggregation: warp per dst, fused den+agg+mean+bias+log_softmax ----------------
__global__ void agg2_kernel(const int* __restrict__ off, const int* __restrict__ srcs,
                            const float* __restrict__ XH,
                            const float* __restrict__ ASRC, const float* __restrict__ ADST,
                            const float* __restrict__ b,
                            float* __restrict__ outLsm, float* __restrict__ outLogits,
                            int N, int writeLogits) {
    int w = (blockIdx.x * blockDim.x + threadIdx.x) >> 5;
    if (w >= N) return;
    int lane  = threadIdx.x & 31;
    int e_sub = lane >> 3;
    int hl    = lane & 7;       // head (alpha) / class pair (dims 2*hl, 2*hl+1)

    int beg = __ldg(off + w);
    int end = __ldg(off + w + 1);
    int niter = (end - beg + 3) >> 2;
    float adst_h = __ldg(ADST + (size_t)w * 8 + hl);

    float den = 0.f;
    for (int it = 0; it < niter; it++) {
        int p = beg + it * 4 + e_sub;
        bool v = p < end;
        int s = __ldg(srcs + (v ? p : beg));
        float e = lrelu_exp(__ldg(ASRC + (size_t)s * 8 + hl) + adst_h);
        den += v ? e : 0.f;
    }
    den += __shfl_xor_sync(0xffffffffu, den, 8);
    den += __shfl_xor_sync(0xffffffffu, den, 16);
    float inv = 1.0f / den;

    float2 acc = make_float2(0.f, 0.f);
    for (int it = 0; it < niter; it++) {
        int p = beg + it * 4 + e_sub;
        bool v = p < end;
        int s = __ldg(srcs + (v ? p : beg));
        float myal = v ? lrelu_exp(__ldg(ASRC + (size_t)s * 8 + hl) + adst_h) * inv : 0.f;
        const float* xr = XH + (size_t)s * 128;
        #pragma unroll
        for (int h = 0; h < 8; h++) {
            float al = __shfl_sync(0xffffffffu, myal, (e_sub << 3) + h);
            float2 xv = __ldg(reinterpret_cast<const float2*>(xr + h * 16) + hl);
            acc.x += al * xv.x; acc.y += al * xv.y;
        }
    }
    #pragma unroll
    for (int s = 8; s <= 16; s <<= 1) {
        acc.x += __shfl_xor_sync(0xffffffffu, acc.x, s);
        acc.y += __shfl_xor_sync(0xffffffffu, acc.y, s);
    }
    // logits for classes 2*hl, 2*hl+1 (valid in all lanes; correct in e_sub 0)
    float l0 = acc.x * 0.125f + __ldg(b + 2 * hl);
    float l1 = acc.y * 0.125f + __ldg(b + 2 * hl + 1);
    float m = fmaxf(l0, l1);
    #pragma unroll
    for (int s = 4; s > 0; s >>= 1) m = fmaxf(m, __shfl_xor_sync(0xffffffffu, m, s));
    float se = expf(l0 - m) + expf(l1 - m);
    #pragma unroll
    for (int s = 4; s > 0; s >>= 1) se += __shfl_xor_sync(0xffffffffu, se, s);
    float lse = m + logf(se);
    if (e_sub == 0) {
        reinterpret_cast<float2*>(outLsm)[(size_t)w * 8 + hl] = make_float2(l0 - lse, l1 - lse);
        if (writeLogits)
            reinterpret_cast<float2*>(outLogits)[(size_t)w * 8 + hl] = make_float2(l0, l1);
    }
}

// ---------------- host launcher ----------------
extern "C" void kernel_launch(void* const* d_in, const int* in_sizes, int n_in,
                              void* d_out, int out_size) {
    const float* x   = (const float*)d_in[0];
    const int*   ei  = (const int*)d_in[1];
    const float* W1  = (const float*)d_in[2];
    const float* as1 = (const float*)d_in[3];
    const float* ad1 = (const float*)d_in[4];
    const float* b1  = (const float*)d_in[5];
    const float* W2  = (const float*)d_in[6];
    const float* as2 = (const float*)d_in[7];
    const float* ad2 = (const float*)d_in[8];
    const float* b2  = (const float*)d_in[9];

    int N  = in_sizes[0] / 128;
    int E  = in_sizes[1] / 2;
    int EN = E + N;
    float* out = (float*)d_out;

    void *xh1, *xh2, *asrc, *adst, *h1, *deg, *off, *cursor, *srcs;
    cudaGetSymbolAddress(&xh1,  g_xh1);
    cudaGetSymbolAddress(&xh2,  g_xh2);
    cudaGetSymbolAddress(&asrc, g_asrc);
    cudaGetSymbolAddress(&adst, g_adst);
    cudaGetSymbolAddress(&h1,   g_h1);
    cudaGetSymbolAddress(&deg,    g_deg);
    cudaGetSymbolAddress(&off,    g_off);
    cudaGetSymbolAddress(&cursor, g_cursor);
    cudaGetSymbolAddress(&srcs,   g_srcs);

    const int smem1 = (128 * 128 + 64 * 128) * 4;   // 96 KB
    const int smem2 = (32 * 128 + 64 * 32) * 4;     // 24 KB
    cudaFuncSetAttribute(gemm_att_kernel<128, 256, 32>,
                         cudaFuncAttributeMaxDynamicSharedMemorySize, smem1);

    // ---- CSR build (shared by both layers) ----
    cudaMemsetAsync(deg, 0, N * sizeof(int), 0);
    hist_kernel<<<512, 256>>>(ei, E, (int*)deg);                              // 1
    scan_kernel<<<1, 1024>>>((int*)deg, (int*)off, N);                        // 2
    copy_kernel<<<(N + 255) / 256, 256>>>((int*)off, (int*)cursor, N);        // 3
    scatter_kernel<<<(EN + 511) / 512, 512>>>(ei, E, N, (int*)cursor, (int*)srcs); // 4

    // ---- layer 1 ----
    gemm_att_kernel<128, 256, 32><<<dim3((N + 63) / 64, 2), 512, smem1>>>(
        x, W1, as1, ad1, (float*)xh1, (float*)asrc, (float*)adst, N);         // 5
    agg1_kernel<<<((size_t)N * 32 + 255) / 256, 256>>>(
        (int*)off, (int*)srcs, (float*)xh1, (float*)asrc, (float*)adst,
        b1, (float*)h1, N);                                                   // 6 <- profiled

    // ---- layer 2 ----
    gemm_att_kernel<32, 128, 16><<<dim3((N + 63) / 64, 1), 512, smem2>>>(
        (float*)h1, W2, as2, ad2, (float*)xh2, (float*)asrc, (float*)adst, N);
    int wl = (out_size >= 2 * N * 16) ? 1 : 0;
    agg2_kernel<<<((size_t)N * 32 + 255) / 256, 256>>>(
        (int*)off, (int*)srcs, (float*)xh2, (float*)asrc, (float*)adst,
        b2, out, out + (size_t)N * 16, N, wl);
}

// round 5
// speedup vs baseline: 1.3975x; 1.3975x over previous
#include <cuda_runtime.h>
#include <cuda_fp16.h>
#include <math.h>

#define NMAX 100000
#define EMAX 1600000
#define HEADS 8

typedef unsigned long long ull;

// ---------------- scratch (static device globals; no runtime alloc) ----------------
__device__ __half g_xh1[(size_t)NMAX * 256];
__device__ __half g_xh2[(size_t)NMAX * 128];
__device__ float  g_agg1[(size_t)NMAX * 32];
__device__ float  g_agg2[(size_t)NMAX * 16];
__device__ float  g_asrc[(size_t)NMAX * HEADS];
__device__ float  g_adst[(size_t)NMAX * HEADS];
__device__ float  g_den[(size_t)2 * NMAX * HEADS];
__device__ float  g_h1[(size_t)NMAX * 32];

// ---------------- helpers ----------------
__device__ __forceinline__ void red_add_v4(float* p, float4 v) {
    asm volatile("red.global.add.v4.f32 [%0], {%1,%2,%3,%4};"
                 :: "l"(p), "f"(v.x), "f"(v.y), "f"(v.z), "f"(v.w)
                 : "memory");
}
__device__ __forceinline__ float lrelu_exp(float v) {
    v = v > 0.0f ? v : 0.2f * v;
    return expf(v);
}
__device__ __forceinline__ ull pack2(float v) {
    ull r; asm("mov.b64 %0, {%1, %1};" : "=l"(r) : "f"(v)); return r;
}
__device__ __forceinline__ void fma2(ull& d, ull a, ull b) {
    asm("fma.rn.f32x2 %0, %1, %2, %0;" : "+l"(d) : "l"(a), "l"(b));
}
__device__ __forceinline__ float2 unpack2(ull v) {
    float2 f; asm("mov.b64 {%0, %1}, %2;" : "=f"(f.x), "=f"(f.y) : "l"(v)); return f;
}

// ---------------- fused GEMM (fp32x2) + attention logits; CO split across gridDim.y ----------------
// block: 512 threads; cg = lane (32 column quads = 128 cols/block), rg = warp (16 x 4 rows = 64 rows).
// XH stored as fp16 (computed fp32).
template<int F, int CO, int HS>
__global__ void __launch_bounds__(512, 2)
gemm_att_kernel(const float* __restrict__ X, const float* __restrict__ W,
                const float* __restrict__ a_src_w, const float* __restrict__ a_dst_w,
                __half* __restrict__ XH, float* __restrict__ ASRC,
                float* __restrict__ ADST, int N) {
    constexpr int GROUP = HS / 4;                 // quads per head
    extern __shared__ float sh[];
    float* Ws = sh;                                // F * 128 floats
    float* Xs = sh + F * 128;                      // 64 * F floats
    float4* Ws4 = reinterpret_cast<float4*>(Ws);
    const ulonglong2* Wsu = reinterpret_cast<const ulonglong2*>(Ws);
    float4* Xs4 = reinterpret_cast<float4*>(Xs);

    const int tid  = threadIdx.x;
    const int cg   = tid & 31;
    const int rg   = tid >> 5;
    const int half = blockIdx.y;
    const int qg   = half * 32 + cg;               // global column quad

    const float4* Wg4 = reinterpret_cast<const float4*>(W);
    for (int i = tid; i < F * 32; i += 512) {
        int f = i >> 5, c = i & 31;
        Ws4[i] = Wg4[(size_t)f * (CO / 4) + half * 32 + c];
    }

    const float4 av_s = reinterpret_cast<const float4*>(a_src_w)[qg];
    const float4 av_d = reinterpret_cast<const float4*>(a_dst_w)[qg];

    const int n0 = blockIdx.x * 64;
    for (int i = tid; i < 64 * F / 4; i += 512) {
        int row  = i / (F / 4);
        int col4 = i % (F / 4);
        int n = n0 + row;
        Xs4[i] = (n < N) ? reinterpret_cast<const float4*>(X)[(size_t)n * (F / 4) + col4]
                         : make_float4(0.f, 0.f, 0.f, 0.f);
    }
    __syncthreads();

    ull acc[4][2];
    #pragma unroll
    for (int r = 0; r < 4; r++) { acc[r][0] = 0ULL; acc[r][1] = 0ULL; }

    #pragma unroll 8
    for (int f = 0; f < F; f++) {
        ulonglong2 w = Wsu[f * 32 + cg];
        #pragma unroll
        for (int r = 0; r < 4; r++) {
            ull xv2 = pack2(Xs[(rg * 4 + r) * F + f]);
            fma2(acc[r][0], xv2, w.x);
            fma2(acc[r][1], xv2, w.y);
        }
    }

    #pragma unroll
    for (int r = 0; r < 4; r++) {
        int n = n0 + rg * 4 + r;
        if (n >= N) continue;
        float2 lo = unpack2(acc[r][0]);
        float2 hi = unpack2(acc[r][1]);
        float4 o = make_float4(lo.x, lo.y, hi.x, hi.y);
        __half2 p0 = __floats2half2_rn(o.x, o.y);
        __half2 p1 = __floats2half2_rn(o.z, o.w);
        uint2 u = make_uint2(*reinterpret_cast<unsigned*>(&p0),
                             *reinterpret_cast<unsigned*>(&p1));
        reinterpret_cast<uint2*>(XH)[(size_t)n * (CO / 4) + qg] = u;
        float ps = o.x * av_s.x + o.y * av_s.y + o.z * av_s.z + o.w * av_s.w;
        float pd = o.x * av_d.x + o.y * av_d.y + o.z * av_d.z + o.w * av_d.w;
        #pragma unroll
        for (int s = GROUP / 2; s > 0; s >>= 1) {
            ps += __shfl_xor_sync(0xffffffffu, ps, s);
            pd += __shfl_xor_sync(0xffffffffu, pd, s);
        }
        if ((cg & (GROUP - 1)) == 0) {
            int h = qg / GROUP;
            ASRC[(size_t)n * HEADS + h] = ps;
            ADST[(size_t)n * HEADS + h] = pd;
        }
    }
}

// ---------------- denominator pass ----------------
__global__ void den_kernel(const int* __restrict__ ei, int E, int N,
                           const float* __restrict__ ASRC, const float* __restrict__ ADST,
                           float* __restrict__ DEN) {
    int k = blockIdx.x * blockDim.x + threadIdx.x;
    int EN = E + N;
    if (k >= EN) return;
    int src, dst;
    if (k < E) { src = __ldg(ei + k); dst = __ldg(ei + E + k); }
    else       { src = dst = k - E; }

    float4 a0 = __ldg(reinterpret_cast<const float4*>(ASRC) + (size_t)src * 2 + 0);
    float4 a1 = __ldg(reinterpret_cast<const float4*>(ASRC) + (size_t)src * 2 + 1);
    float4 b0 = __ldg(reinterpret_cast<const float4*>(ADST) + (size_t)dst * 2 + 0);
    float4 b1 = __ldg(reinterpret_cast<const float4*>(ADST) + (size_t)dst * 2 + 1);

    float4 e0, e1;
    e0.x = lrelu_exp(a0.x + b0.x); e0.y = lrelu_exp(a0.y + b0.y);
    e0.z = lrelu_exp(a0.z + b0.z); e0.w = lrelu_exp(a0.w + b0.w);
    e1.x = lrelu_exp(a1.x + b1.x); e1.y = lrelu_exp(a1.y + b1.y);
    e1.z = lrelu_exp(a1.z + b1.z); e1.w = lrelu_exp(a1.w + b1.w);

    red_add_v4(DEN + (size_t)dst * 8 + 0, e0);
    red_add_v4(DEN + (size_t)dst * 8 + 4, e1);
}

// ---------------- aggregate layer 1: 8 lanes/edge; fp16 xh gather ----------------
__global__ void aggregate1_kernel(const int* __restrict__ ei, int E, int N,
                                  const __half* __restrict__ XH,
                                  const float* __restrict__ ASRC, const float* __restrict__ ADST,
                                  const float* __restrict__ DEN, float* __restrict__ AGG) {
    int t = blockIdx.x * blockDim.x + threadIdx.x;
    int k = t >> 3;
    int l = t & 7;
    int EN = E + N;
    bool valid = k < EN;
    if (!valid) k = 0;
    int src, dst;
    if (k < E) { src = __ldg(ei + k); dst = __ldg(ei + E + k); }
    else       { src = dst = k - E; }

    float alpha_l = lrelu_exp(__ldg(ASRC + (size_t)src * 8 + l) + __ldg(ADST + (size_t)dst * 8 + l))
                    / __ldg(DEN + (size_t)dst * 8 + l);

    const uint2* xs = reinterpret_cast<const uint2*>(XH) + (size_t)src * 64;
    float4 acc = make_float4(0.f, 0.f, 0.f, 0.f);
    #pragma unroll
    for (int h = 0; h < 8; h++) {
        float alpha = __shfl_sync(0xffffffffu, alpha_l, h, 8);
        uint2 u = __ldg(xs + h * 8 + l);
        float2 f0 = __half22float2(*reinterpret_cast<__half2*>(&u.x));
        float2 f1 = __half22float2(*reinterpret_cast<__half2*>(&u.y));
        acc.x += alpha * f0.x; acc.y += alpha * f0.y;
        acc.z += alpha * f1.x; acc.w += alpha * f1.y;
    }
    if (valid) red_add_v4(AGG + (size_t)dst * 32 + l * 4, acc);
}

// ---------------- aggregate layer 2: 4 lanes/edge; fp16 xh gather ----------------
__global__ void aggregate2_kernel(const int* __restrict__ ei, int E, int N,
                                  const __half* __restrict__ XH,
                                  const float* __restrict__ ASRC, const float* __restrict__ ADST,
                                  const float* __restrict__ DEN, float* __restrict__ AGG) {
    int t = blockIdx.x * blockDim.x + threadIdx.x;
    int k = t >> 2;
    int l = t & 3;
    int EN = E + N;
    bool valid = k < EN;
    if (!valid) k = 0;
    int src, dst;
    if (k < E) { src = __ldg(ei + k); dst = __ldg(ei + E + k); }
    else       { src = dst = k - E; }

    float a0 = lrelu_exp(__ldg(ASRC + (size_t)src * 8 + l) + __ldg(ADST + (size_t)dst * 8 + l))
               / __ldg(DEN + (size_t)dst * 8 + l);
    float a1 = lrelu_exp(__ldg(ASRC + (size_t)src * 8 + l + 4) + __ldg(ADST + (size_t)dst * 8 + l + 4))
               / __ldg(DEN + (size_t)dst * 8 + l + 4);

    const uint2* xs = reinterpret_cast<const uint2*>(XH) + (size_t)src * 32;
    float4 acc = make_float4(0.f, 0.f, 0.f, 0.f);
    #pragma unroll
    for (int h = 0; h < 8; h++) {
        float alpha = (h < 4) ? __shfl_sync(0xffffffffu, a0, h, 4)
                              : __shfl_sync(0xffffffffu, a1, h - 4, 4);
        uint2 u = __ldg(xs + h * 4 + l);
        float2 f0 = __half22float2(*reinterpret_cast<__half2*>(&u.x));
        float2 f1 = __half22float2(*reinterpret_cast<__half2*>(&u.y));
        acc.x += alpha * f0.x; acc.y += alpha * f0.y;
        acc.z += alpha * f1.x; acc.w += alpha * f1.y;
    }
    if (valid) red_add_v4(AGG + (size_t)dst * 16 + l * 4, acc);
}

// ---------------- finalize layer 1 ----------------
__global__ void finalize1_kernel(const float* __restrict__ agg, const float* __restrict__ b,
                                 float* __restrict__ out, int N) {
    int i = blockIdx.x * blockDim.x + threadIdx.x;
    if (i >= N * 32) return;
    int d = i & 31;
    float m = agg[i] * 0.125f + __ldg(b + d);
    out[i] = m > 0.f ? m : (expf(m) - 1.0f);
}

// ---------------- finalize layer 2 ----------------
__global__ void finalize2_kernel(const float* __restrict__ agg, const float* __restrict__ b,
                                 float* __restrict__ outLsm, float* __restrict__ outLogits,
                                 int N, int writeLogits) {
    int gid = blockIdx.x * blockDim.x + threadIdx.x;
    int n = gid >> 4, c = gid & 15;
    bool valid = n < N;
    float l = 0.f;
    if (valid) l = agg[gid] * 0.125f + __ldg(b + c);
    float m = l;
    #pragma unroll
    for (int s = 8; s > 0; s >>= 1) m = fmaxf(m, __shfl_xor_sync(0xffffffffu, m, s));
    float e = expf(l - m);
    float se = e;
    #pragma unroll
    for (int s = 8; s > 0; s >>= 1) se += __shfl_xor_sync(0xffffffffu, se, s);
    if (valid) {
        outLsm[gid] = l - m - logf(se);
        if (writeLogits) outLogits[gid] = l;
    }
}

// ---------------- host launcher ----------------
extern "C" void kernel_launch(void* const* d_in, const int* in_sizes, int n_in,
                              void* d_out, int out_size) {
    const float* x   = (const float*)d_in[0];
    const int*   ei  = (const int*)d_in[1];
    const float* W1  = (const float*)d_in[2];
    const float* as1 = (const float*)d_in[3];
    const float* ad1 = (const float*)d_in[4];
    const float* b1  = (const float*)d_in[5];
    const float* W2  = (const float*)d_in[6];
    const float* as2 = (const float*)d_in[7];
    const float* ad2 = (const float*)d_in[8];
    const float* b2  = (const float*)d_in[9];

    int N  = in_sizes[0] / 128;
    int E  = in_sizes[1] / 2;
    int EN = E + N;
    float* out = (float*)d_out;

    void *xh1, *xh2, *agg1, *agg2, *asrc, *adst, *den, *h1;
    cudaGetSymbolAddress(&xh1,  g_xh1);
    cudaGetSymbolAddress(&xh2,  g_xh2);
    cudaGetSymbolAddress(&agg1, g_agg1);
    cudaGetSymbolAddress(&agg2, g_agg2);
    cudaGetSymbolAddress(&asrc, g_asrc);
    cudaGetSymbolAddress(&adst, g_adst);
    cudaGetSymbolAddress(&den,  g_den);
    cudaGetSymbolAddress(&h1,   g_h1);

    float* den1 = (float*)den;
    float* den2 = (float*)den + (size_t)N * 8;

    const int smem1 = (128 * 128 + 64 * 128) * 4;   // 96 KB
    const int smem2 = (32 * 128 + 64 * 32) * 4;     // 24 KB
    cudaFuncSetAttribute(gemm_att_kernel<128, 256, 32>,
                         cudaFuncAttributeMaxDynamicSharedMemorySize, smem1);

    // launches 1-5: zeroing (positions gemm1 at launch #6 for ncu -s 5 -c 1)
    cudaMemsetAsync(den1, 0, (size_t)N * 8 * sizeof(float), 0);   // 1
    cudaMemsetAsync(den2, 0, (size_t)N * 8 * sizeof(float), 0);   // 2
    cudaMemsetAsync(agg1, 0, (size_t)N * 32 * sizeof(float), 0);  // 3
    cudaMemsetAsync(agg2, 0, (size_t)N * 16 * sizeof(float), 0);  // 4
    cudaMemsetAsync(asrc, 0, (size_t)N * 8 * sizeof(float), 0);   // 5 (overwritten; ordering filler)

    // ---- layer 1 ----
    gemm_att_kernel<128, 256, 32><<<dim3((N + 63) / 64, 2), 512, smem1>>>(
        x, W1, as1, ad1, (__half*)xh1, (float*)asrc, (float*)adst, N);        // 6 <- profiled
    den_kernel<<<(EN + 255) / 256, 256>>>(ei, E, N, (float*)asrc, (float*)adst, den1);
    aggregate1_kernel<<<((size_t)EN * 8 + 255) / 256, 256>>>(
        ei, E, N, (__half*)xh1, (float*)asrc, (float*)adst, den1, (float*)agg1);
    finalize1_kernel<<<(N * 32 + 255) / 256, 256>>>((float*)agg1, b1, (float*)h1, N);

    // ---- layer 2 ----
    gemm_att_kernel<32, 128, 16><<<dim3((N + 63) / 64, 1), 512, smem2>>>(
        (float*)h1, W2, as2, ad2, (__half*)xh2, (float*)asrc, (float*)adst, N);
    den_kernel<<<(EN + 255) / 256, 256>>>(ei, E, N, (float*)asrc, (float*)adst, den2);
    aggregate2_kernel<<<((size_t)EN * 4 + 255) / 256, 256>>>(
        ei, E, N, (__half*)xh2, (float*)asrc, (float*)adst, den2, (float*)agg2);

    int wl = (out_size >= 2 * N * 16) ? 1 : 0;
    finalize2_kernel<<<(N * 16 + 127) / 128, 128>>>((float*)agg2, b2,
                                                    out, out + (size_t)N * 16, N, wl);
}